// round 5
// baseline (speedup 1.0000x reference)
#include <cuda_runtime.h>
#include <cuda_fp16.h>

#define BN   4
#define NF   8
#define CC   8
#define NPIX (512 * 512)
#define NG   (NPIX / 4)              // 65536 pixel-groups per image
#define BPI  37                      // blocks per image
#define NBLK (BN * BPI)              // 148 = one block per SM
#define NGB  ((NG + BPI - 1) / BPI)  // 1772 groups per block
#define NTHR 1024
#define PAIRS (NTHR / 2)             // 512 pairs per block
#define ITER ((NGB + PAIRS - 1) / PAIRS)  // 4

#define SMEM_PRED_BYTES (NGB * 4 * 16)              // 113408 B
#define SMEM_TOTAL      (SMEM_PRED_BYTES + NGB * 4) // + packed labels

typedef unsigned long long ULL;

struct Scratch {
    float sums[BN][CC][NF];
    float counts[BN][CC];
    float dist[BN];
    unsigned int arrive;
    unsigned int release;
    unsigned int ticket;
};
__device__ Scratch g_s;

__device__ __forceinline__ ULL fadd2(ULL a, ULL b) {
    ULL d;
    asm("add.rn.f32x2 %0, %1, %2;" : "=l"(d) : "l"(a), "l"(b));
    return d;
}
__device__ __forceinline__ ULL pack2(float lo, float hi) {
    ULL r;
    asm("mov.b64 %0, {%1, %2};" : "=l"(r) : "f"(lo), "f"(hi));
    return r;
}
__device__ __forceinline__ void unpack2(ULL v, float& lo, float& hi) {
    asm("mov.b64 {%0, %1}, %2;" : "=f"(lo), "=f"(hi) : "l"(v));
}
// if (lab == c): a0 += p0; a1 += p1; cnt += inc  (one setp, three predicated adds)
__device__ __forceinline__ void acc_if_eq(ULL& a0, ULL& a1, int& cnt,
                                          int lab, int c, int inc,
                                          ULL p0, ULL p1) {
    asm("{ .reg .pred p; setp.eq.s32 p, %3, %4;\n\t"
        "@p add.rn.f32x2 %0, %0, %6;\n\t"
        "@p add.rn.f32x2 %1, %1, %7;\n\t"
        "@p add.s32 %2, %2, %5; }"
        : "+l"(a0), "+l"(a1), "+r"(cnt)
        : "r"(lab), "r"(c), "r"(inc), "l"(p0), "l"(p1));
}
__device__ __forceinline__ float f4get(const float4 v, int i) {
    return i == 0 ? v.x : i == 1 ? v.y : i == 2 ? v.z : v.w;
}
__device__ __forceinline__ int i4get(const int4 v, int i) {
    return i == 0 ? v.x : i == 1 ? v.y : i == 2 ? v.z : v.w;
}
__device__ __forceinline__ unsigned h2u(__half2 h) {
    return *reinterpret_cast<unsigned*>(&h);
}
__device__ __forceinline__ float2 u2f2(unsigned u) {
    return __half22float2(*reinterpret_cast<__half2*>(&u));
}

__global__ void __launch_bounds__(NTHR, 1)
k_all(const float* __restrict__ pred, const int* __restrict__ tgt,
      float* __restrict__ out) {
    extern __shared__ unsigned char smem_raw[];
    uint4*    spred = (uint4*)smem_raw;                          // [NGB*4]
    unsigned* slab  = (unsigned*)(smem_raw + SMEM_PRED_BYTES);   // [NGB]

    const int tid  = threadIdx.x;
    const int pair = tid >> 1;
    const int half = tid & 1;            // 0: features 0-3, 1: features 4-7
    const int bx   = blockIdx.x;
    const int img  = bx / BPI;
    const int li   = bx % BPI;
    const int g0   = li * NGB;
    const int g1   = (g0 + NGB < NG) ? g0 + NGB : NG;

    const float4* p = (const float4*)(pred + (size_t)img * NF * NPIX) +
                      (size_t)(half * 4) * NG;
    const int4*   g = (const int4*)(tgt + (size_t)img * NPIX);

    // ================= Phase A: load once, accumulate, cache fp16 ==========
    ULL acc[CC][2];          // [cluster][feature-pair within this half]
    int cnta = 0, cntb = 0;  // packed byte counters: clusters 0-3 / 4-7
#pragma unroll
    for (int c = 0; c < CC; c++) { acc[c][0] = 0ull; acc[c][1] = 0ull; }

#pragma unroll
    for (int it = 0; it < ITER; it++) {
        int n = g0 + pair + it * PAIRS;
        bool act = (n < g1);
        int nn = act ? n : g0;
        int gl = nn - g0;

        int4 lab4 = g[nn];
        float4 v0 = p[0 * NG + nn];
        float4 v1 = p[1 * NG + nn];
        float4 v2 = p[2 * NG + nn];
        float4 v3 = p[3 * NG + nn];

        if (act && half == 0)
            slab[gl] = (unsigned)(lab4.x) | ((unsigned)(lab4.y) << 8) |
                       ((unsigned)(lab4.z) << 16) | ((unsigned)(lab4.w) << 24);

        // fp16 cache: 2 uint4 per thread per group
        if (act) {
            uint4 ha, hb;
            ha.x = h2u(__floats2half2_rn(v0.x, v1.x));
            ha.y = h2u(__floats2half2_rn(v2.x, v3.x));
            ha.z = h2u(__floats2half2_rn(v0.y, v1.y));
            ha.w = h2u(__floats2half2_rn(v2.y, v3.y));
            hb.x = h2u(__floats2half2_rn(v0.z, v1.z));
            hb.y = h2u(__floats2half2_rn(v2.z, v3.z));
            hb.z = h2u(__floats2half2_rn(v0.w, v1.w));
            hb.w = h2u(__floats2half2_rn(v2.w, v3.w));
            spred[gl * 4 + half * 2 + 0] = ha;
            spred[gl * 4 + half * 2 + 1] = hb;
        }

#pragma unroll
        for (int px = 0; px < 4; px++) {
            int lab = act ? i4get(lab4, px) : 255;
            ULL pr0 = pack2(f4get(v0, px), f4get(v1, px));
            ULL pr1 = pack2(f4get(v2, px), f4get(v3, px));
#pragma unroll
            for (int c = 0; c < 4; c++)
                acc_if_eq(acc[c][0], acc[c][1], cnta, lab, c, 1 << (8 * c),
                          pr0, pr1);
#pragma unroll
            for (int c = 4; c < 8; c++)
                acc_if_eq(acc[c][0], acc[c][1], cntb, lab, c, 1 << (8 * (c - 4)),
                          pr0, pr1);
        }
    }

    // parity-preserving warp reduce of packed sums (offsets 16,8,4,2)
    int icnt[CC];
#pragma unroll
    for (int c = 0; c < 4; c++) {
        icnt[c]     = (cnta >> (8 * c)) & 0xFF;
        icnt[c + 4] = (cntb >> (8 * c)) & 0xFF;
    }
#pragma unroll
    for (int c = 0; c < CC; c++) {
#pragma unroll
        for (int k = 0; k < 2; k++) {
            ULL x = acc[c][k];
            x = fadd2(x, __shfl_down_sync(0xffffffffu, x, 16));
            x = fadd2(x, __shfl_down_sync(0xffffffffu, x, 8));
            x = fadd2(x, __shfl_down_sync(0xffffffffu, x, 4));
            x = fadd2(x, __shfl_down_sync(0xffffffffu, x, 2));
            acc[c][k] = x;
        }
        int ic = icnt[c];
#pragma unroll
        for (int o = 16; o > 0; o >>= 1) ic += __shfl_down_sync(0xffffffffu, ic, o);
        icnt[c] = ic;
    }

    __shared__ float sw[32][72];   // 32 warps x (64 sums + 8 counts)
    int wid = tid >> 5, lane = tid & 31;
    if (lane < 2) {                // lane0: even-parity (f0-3), lane1: f4-7
#pragma unroll
        for (int c = 0; c < CC; c++) {
#pragma unroll
            for (int k = 0; k < 2; k++) {
                float lo, hi;
                unpack2(acc[c][k], lo, hi);
                sw[wid][c * NF + lane * 4 + 2 * k]     = lo;
                sw[wid][c * NF + lane * 4 + 2 * k + 1] = hi;
            }
        }
        if (lane == 0)
#pragma unroll
            for (int c = 0; c < CC; c++)
                sw[wid][64 + c] = 0.5f * (float)icnt[c];  // both halves counted
    }
    __syncthreads();
    if (tid < 72) {
        float s = 0.f;
#pragma unroll
        for (int w = 0; w < 32; w++) s += sw[w][tid];
        if (tid < 64)
            atomicAdd(&((float*)g_s.sums)[img * 64 + tid], s);
        else
            atomicAdd(&g_s.counts[img][tid - 64], s);
    }
    __threadfence();
    __syncthreads();

    // ================= Grid barrier (148 resident blocks) ==================
    if (tid == 0) {
        unsigned int a = atomicAdd(&g_s.arrive, 1u);
        if (a == NBLK - 1) {
            atomicExch(&g_s.release, 1u);
        } else {
            volatile unsigned int* rel = &g_s.release;
            while (*rel == 0u) { __nanosleep(64); }
        }
    }
    __syncthreads();
    __threadfence();

    // ================= Phase B: hinge distance from smem fp16 ==============
    __shared__ float smean[NF][CC];
    if (tid < 64) {
        int c = tid & 7, f = tid >> 3;
        smean[f][c] = __ldcg(&g_s.sums[img][c][f]) / __ldcg(&g_s.counts[img][c]);
    }
    __syncthreads();

    const int fb = half * 4;
    float local = 0.f;
#pragma unroll
    for (int it = 0; it < ITER; it++) {
        int n = g0 + pair + it * PAIRS;
        bool act = (n < g1);
        int gl = (act ? n : g0) - g0;
        unsigned lw = slab[gl];
        uint4 ha = spred[gl * 4 + half * 2 + 0];
        uint4 hb = spred[gl * 4 + half * 2 + 1];
#pragma unroll
        for (int px = 0; px < 4; px++) {
            int lab = (lw >> (8 * px)) & 0xFF;
            unsigned u01 = (px == 0) ? ha.x : (px == 1) ? ha.z : (px == 2) ? hb.x : hb.z;
            unsigned u23 = (px == 0) ? ha.y : (px == 1) ? ha.w : (px == 2) ? hb.y : hb.w;
            float2 q01 = u2f2(u01), q23 = u2f2(u23);
            float d2p = 0.f, d;
            d = smean[fb + 0][lab] - q01.x; d2p = fmaf(d, d, d2p);
            d = smean[fb + 1][lab] - q01.y; d2p = fmaf(d, d, d2p);
            d = smean[fb + 2][lab] - q23.x; d2p = fmaf(d, d, d2p);
            d = smean[fb + 3][lab] - q23.y; d2p = fmaf(d, d, d2p);
            float d2 = d2p + __shfl_xor_sync(0xffffffffu, d2p, 1);
            float t = sqrtf(d2) - 0.5f;          // DELTA_V
            t = fminf(fmaxf(t, 0.f), 100000.f);
            if (act) local = fmaf(t, t, local);  // both lanes add -> x0.5 later
        }
    }

#pragma unroll
    for (int o = 16; o > 0; o >>= 1)
        local += __shfl_down_sync(0xffffffffu, local, o);
    __shared__ float sred[32];
    if (lane == 0) sred[wid] = local;
    __syncthreads();
    if (tid == 0) {
        float s = 0.f;
#pragma unroll
        for (int w = 0; w < 32; w++) s += sred[w];
        atomicAdd(&g_s.dist[img], s * 0.5f);
    }

    // ================= Last-block finalize =================================
    __shared__ bool s_last;
    __threadfence();
    if (tid == 0) {
        unsigned int t = atomicAdd(&g_s.ticket, 1u);
        s_last = (t == NBLK - 1);
    }
    __syncthreads();
    if (!s_last) return;

    __shared__ float smu[BN][CC][NF];
    __shared__ float s_ldist[BN], s_lreg[BN], s_inv[BN];
    if (tid < 256) {
        int bb = tid >> 6, i = (tid >> 3) & 7, j = tid & 7;
        smu[bb][i][j] = __ldcg(&g_s.sums[bb][i][j]) / __ldcg(&g_s.counts[bb][i]);
    }
    if (tid < BN) { s_ldist[tid] = 0.f; s_lreg[tid] = 0.f; s_inv[tid] = 0.f; }
    __syncthreads();

    if (tid < 256) {
        int bb = tid >> 6, i = (tid >> 3) & 7, j = tid & 7;
        if (i != j) {
            float d2 = 0.f;
#pragma unroll
            for (int f = 0; f < NF; f++) {
                float d = smu[bb][i][f] - smu[bb][j][f];
                d2 = fmaf(d, d, d2);
            }
            float t = 3.0f - sqrtf(d2);          // 2 * DELTA_D
            t = fminf(fmaxf(t, 0.f), 100000.f);
            atomicAdd(&s_ldist[bb], t * t);
        } else {
            float d2 = 0.f;
#pragma unroll
            for (int f = 0; f < NF; f++)
                d2 = fmaf(smu[bb][i][f], smu[bb][i][f], d2);
            atomicAdd(&s_lreg[bb], sqrtf(d2));
            atomicAdd(&s_inv[bb], 1.0f / __ldcg(&g_s.counts[bb][i]));
        }
    }
    __syncthreads();

    if (tid == 0) {
        float total = 0.f;
#pragma unroll
        for (int q = 0; q < BN; q++) {
            float dq = __ldcg(&g_s.dist[q]);
            float l_var  = dq * s_inv[q] / (float)CC;
            float l_dist = s_ldist[q] / (float)(CC * (CC - 1));
            float l_reg  = s_lreg[q] / (float)CC;
            total += l_var + l_dist + 0.001f * l_reg;
        }
        out[0] = total / (float)BN;
    }
}

extern "C" void kernel_launch(void* const* d_in, const int* in_sizes, int n_in,
                              void* d_out, int out_size) {
    const float* pred = (const float*)d_in[0];
    const int*   tgt  = (const int*)d_in[1];
    float*       out  = (float*)d_out;
    (void)in_sizes; (void)n_in; (void)out_size;

    static bool attr_done = false;
    if (!attr_done) {
        cudaFuncSetAttribute(k_all, cudaFuncAttributeMaxDynamicSharedMemorySize,
                             SMEM_TOTAL);
        attr_done = true;
    }

    void* scratch_ptr = nullptr;
    cudaGetSymbolAddress(&scratch_ptr, g_s);
    cudaMemsetAsync(scratch_ptr, 0, sizeof(Scratch));

    k_all<<<NBLK, NTHR, SMEM_TOTAL>>>(pred, tgt, out);
}

// round 6
// speedup vs baseline: 1.0333x; 1.0333x over previous
#include <cuda_runtime.h>

#define BN   4
#define NF   8
#define CC   8
#define NPIX (512 * 512)
#define NG   (NPIX / 4)

#define P1_BLKX 148
#define P1_THR  128
#define P2_BLKX 296
#define P2_THR  128
#define P2_TOTAL (P2_BLKX * BN)

typedef unsigned long long ULL;

struct Scratch {
    float sums[BN][CC][NF];
    float counts[BN][CC];
    float dist[BN];
    unsigned int ticket;
};
__device__ Scratch g_s;

__device__ __forceinline__ ULL fadd2(ULL a, ULL b) {
    ULL d;
    asm("add.rn.f32x2 %0, %1, %2;" : "=l"(d) : "l"(a), "l"(b));
    return d;
}
__device__ __forceinline__ ULL pack2(float lo, float hi) {
    ULL r;
    asm("mov.b64 %0, {%1, %2};" : "=l"(r) : "f"(lo), "f"(hi));
    return r;
}
__device__ __forceinline__ void unpack2(ULL v, float& lo, float& hi) {
    asm("mov.b64 {%0, %1}, %2;" : "=f"(lo), "=f"(hi) : "l"(v));
}
// if (lab == c): acc0..3 += pr0..3 (f32x2 each), cnt += inc. 1 setp + 5 pred adds.
__device__ __forceinline__ void acc_if_eq(ULL& a0, ULL& a1, ULL& a2, ULL& a3,
                                          int& cnt, int lab, int c, int inc,
                                          ULL p0, ULL p1, ULL p2, ULL p3) {
    asm("{ .reg .pred p; setp.eq.s32 p, %5, %6;\n\t"
        "@p add.rn.f32x2 %0, %0, %8;\n\t"
        "@p add.rn.f32x2 %1, %1, %9;\n\t"
        "@p add.rn.f32x2 %2, %2, %10;\n\t"
        "@p add.rn.f32x2 %3, %3, %11;\n\t"
        "@p add.s32 %4, %4, %7; }"
        : "+l"(a0), "+l"(a1), "+l"(a2), "+l"(a3), "+r"(cnt)
        : "r"(lab), "r"(c), "r"(inc), "l"(p0), "l"(p1), "l"(p2), "l"(p3));
}
__device__ __forceinline__ float f4get(const float4 v, int i) {
    return i == 0 ? v.x : i == 1 ? v.y : i == 2 ? v.z : v.w;
}
__device__ __forceinline__ int i4get(const int4 v, int i) {
    return i == 0 ? v.x : i == 1 ? v.y : i == 2 ? v.z : v.w;
}

// ---------------------------------------------------------------------------
// Pass 1: per-cluster counts + feature sums (predicated-add one-hot).
// ---------------------------------------------------------------------------
__global__ void __launch_bounds__(P1_THR) k_pass1(const float* __restrict__ pred,
                                                  const int* __restrict__ tgt) {
    const int b = blockIdx.y;
    const float4* p = (const float4*)(pred + (size_t)b * NF * NPIX);
    const int4*   g = (const int4*)(tgt + (size_t)b * NPIX);

    ULL acc[CC][4];
    int cnta = 0, cntb = 0;  // byte-packed counts, clusters 0-3 / 4-7
#pragma unroll
    for (int c = 0; c < CC; c++)
#pragma unroll
        for (int k = 0; k < 4; k++) acc[c][k] = 0ull;

    for (int n = blockIdx.x * P1_THR + threadIdx.x; n < NG;
         n += P1_BLKX * P1_THR) {
        int4 lab4 = g[n];
        float4 v[NF];
#pragma unroll
        for (int f = 0; f < NF; f++) v[f] = p[f * NG + n];
#pragma unroll
        for (int px = 0; px < 4; px++) {
            int lab = i4get(lab4, px);
            ULL pr0 = pack2(f4get(v[0], px), f4get(v[1], px));
            ULL pr1 = pack2(f4get(v[2], px), f4get(v[3], px));
            ULL pr2 = pack2(f4get(v[4], px), f4get(v[5], px));
            ULL pr3 = pack2(f4get(v[6], px), f4get(v[7], px));
#pragma unroll
            for (int c = 0; c < 4; c++)
                acc_if_eq(acc[c][0], acc[c][1], acc[c][2], acc[c][3],
                          cnta, lab, c, 1 << (8 * c), pr0, pr1, pr2, pr3);
#pragma unroll
            for (int c = 4; c < 8; c++)
                acc_if_eq(acc[c][0], acc[c][1], acc[c][2], acc[c][3],
                          cntb, lab, c, 1 << (8 * (c - 4)), pr0, pr1, pr2, pr3);
        }
    }

    // unpack counts, warp tree-reduce everything
    int icnt[CC];
#pragma unroll
    for (int c = 0; c < 4; c++) {
        icnt[c]     = (cnta >> (8 * c)) & 0xFF;
        icnt[c + 4] = (cntb >> (8 * c)) & 0xFF;
    }
#pragma unroll
    for (int c = 0; c < CC; c++) {
#pragma unroll
        for (int k = 0; k < 4; k++) {
            ULL x = acc[c][k];
#pragma unroll
            for (int o = 16; o > 0; o >>= 1)
                x = fadd2(x, __shfl_down_sync(0xffffffffu, x, o));
            acc[c][k] = x;
        }
        int ic = icnt[c];
#pragma unroll
        for (int o = 16; o > 0; o >>= 1) ic += __shfl_down_sync(0xffffffffu, ic, o);
        icnt[c] = ic;
    }

    __shared__ float sw[4][72];
    int tid = threadIdx.x, wid = tid >> 5, lane = tid & 31;
    if (lane == 0) {
#pragma unroll
        for (int c = 0; c < CC; c++) {
#pragma unroll
            for (int k = 0; k < 4; k++) {
                float lo, hi;
                unpack2(acc[c][k], lo, hi);
                sw[wid][c * NF + 2 * k]     = lo;
                sw[wid][c * NF + 2 * k + 1] = hi;
            }
            sw[wid][64 + c] = (float)icnt[c];
        }
    }
    __syncthreads();
    if (tid < 72) {
        float s = sw[0][tid] + sw[1][tid] + sw[2][tid] + sw[3][tid];
        if (tid < 64)
            atomicAdd(&((float*)g_s.sums)[b * 64 + tid], s);
        else
            atomicAdd(&g_s.counts[b][tid - 64], s);
    }
}

// ---------------------------------------------------------------------------
// Pass 2: hinge distance to own-cluster mean (float4 mean tables) + finalize.
// ---------------------------------------------------------------------------
__global__ void __launch_bounds__(P2_THR) k_pass2(const float* __restrict__ pred,
                                                  const int* __restrict__ tgt,
                                                  float* __restrict__ out) {
    const int b = blockIdx.y;
    __shared__ float4 smean0[CC];  // features 0-3 per label: 32 words, 32 banks
    __shared__ float4 smean1[CC];  // features 4-7 per label
    int tid = threadIdx.x;
    if (tid < 64) {
        int c = tid >> 3, f = tid & 7;
        float m = g_s.sums[b][c][f] / g_s.counts[b][c];
        float* base = (f < 4) ? (float*)&smean0[c] : (float*)&smean1[c];
        base[f & 3] = m;
    }
    __syncthreads();

    const float4* p = (const float4*)(pred + (size_t)b * NF * NPIX);
    const int4*   g = (const int4*)(tgt + (size_t)b * NPIX);
    float local = 0.f;
    for (int n = blockIdx.x * P2_THR + tid; n < NG; n += P2_BLKX * P2_THR) {
        int4 lab4 = g[n];
        float4 v[NF];
#pragma unroll
        for (int f = 0; f < NF; f++) v[f] = p[f * NG + n];
#pragma unroll
        for (int px = 0; px < 4; px++) {
            int lab = i4get(lab4, px);
            float4 m0 = smean0[lab];
            float4 m1 = smean1[lab];
            float d2 = 0.f, d;
            d = m0.x - f4get(v[0], px); d2 = fmaf(d, d, d2);
            d = m0.y - f4get(v[1], px); d2 = fmaf(d, d, d2);
            d = m0.z - f4get(v[2], px); d2 = fmaf(d, d, d2);
            d = m0.w - f4get(v[3], px); d2 = fmaf(d, d, d2);
            d = m1.x - f4get(v[4], px); d2 = fmaf(d, d, d2);
            d = m1.y - f4get(v[5], px); d2 = fmaf(d, d, d2);
            d = m1.z - f4get(v[6], px); d2 = fmaf(d, d, d2);
            d = m1.w - f4get(v[7], px); d2 = fmaf(d, d, d2);
            float t = sqrtf(d2) - 0.5f;          // DELTA_V
            t = fminf(fmaxf(t, 0.f), 100000.f);
            local = fmaf(t, t, local);
        }
    }

#pragma unroll
    for (int o = 16; o > 0; o >>= 1)
        local += __shfl_down_sync(0xffffffffu, local, o);
    __shared__ float sred[4];
    int wid = tid >> 5, lane = tid & 31;
    if (lane == 0) sred[wid] = local;
    __syncthreads();
    if (tid == 0) {
        float s = sred[0] + sred[1] + sred[2] + sred[3];
        atomicAdd(&g_s.dist[b], s);
    }

    // ---- last-block finalize ----
    __shared__ bool s_last;
    __threadfence();
    if (tid == 0) {
        unsigned int t = atomicAdd(&g_s.ticket, 1u);
        s_last = (t == P2_TOTAL - 1);
    }
    __syncthreads();
    if (!s_last) return;

    __shared__ float smu[BN][CC][NF];
    __shared__ float s_ldist[BN], s_lreg[BN], s_inv[BN];
    {
        int t2 = tid;                 // 128 threads cover 256 (b,c,f) in 2 halves
        int bb = t2 >> 6, i = (t2 >> 3) & 7, j = t2 & 7;
        smu[bb][i][j]     = __ldcg(&g_s.sums[bb][i][j]) / __ldcg(&g_s.counts[bb][i]);
        smu[bb + 2][i][j] = __ldcg(&g_s.sums[bb + 2][i][j]) / __ldcg(&g_s.counts[bb + 2][i]);
    }
    if (tid < BN) { s_ldist[tid] = 0.f; s_lreg[tid] = 0.f; s_inv[tid] = 0.f; }
    __syncthreads();

#pragma unroll
    for (int half = 0; half < 2; half++) {
        int t2 = tid + half * 128;
        int bb = t2 >> 6, i = (t2 >> 3) & 7, j = t2 & 7;
        if (i != j) {
            float d2 = 0.f;
#pragma unroll
            for (int f = 0; f < NF; f++) {
                float d = smu[bb][i][f] - smu[bb][j][f];
                d2 = fmaf(d, d, d2);
            }
            float t = 3.0f - sqrtf(d2);          // 2 * DELTA_D
            t = fminf(fmaxf(t, 0.f), 100000.f);
            atomicAdd(&s_ldist[bb], t * t);
        } else {
            float d2 = 0.f;
#pragma unroll
            for (int f = 0; f < NF; f++)
                d2 = fmaf(smu[bb][i][f], smu[bb][i][f], d2);
            atomicAdd(&s_lreg[bb], sqrtf(d2));
            atomicAdd(&s_inv[bb], 1.0f / __ldcg(&g_s.counts[bb][i]));
        }
    }
    __syncthreads();

    if (tid == 0) {
        float total = 0.f;
#pragma unroll
        for (int q = 0; q < BN; q++) {
            float dq = __ldcg(&g_s.dist[q]);
            float l_var  = dq * s_inv[q] / (float)CC;
            float l_dist = s_ldist[q] / (float)(CC * (CC - 1));
            float l_reg  = s_lreg[q] / (float)CC;
            total += l_var + l_dist + 0.001f * l_reg;
        }
        out[0] = total / (float)BN;
    }
}

extern "C" void kernel_launch(void* const* d_in, const int* in_sizes, int n_in,
                              void* d_out, int out_size) {
    const float* pred = (const float*)d_in[0];
    const int*   tgt  = (const int*)d_in[1];
    float*       out  = (float*)d_out;
    (void)in_sizes; (void)n_in; (void)out_size;

    void* scratch_ptr = nullptr;
    cudaGetSymbolAddress(&scratch_ptr, g_s);
    cudaMemsetAsync(scratch_ptr, 0, sizeof(Scratch));

    dim3 grid1(P1_BLKX, BN);
    k_pass1<<<grid1, P1_THR>>>(pred, tgt);
    dim3 grid2(P2_BLKX, BN);
    k_pass2<<<grid2, P2_THR>>>(pred, tgt, out);
}

// round 7
// speedup vs baseline: 1.0452x; 1.0116x over previous
#include <cuda_runtime.h>

#define BN   4
#define NF   8
#define CC   8
#define NPIX (512 * 512)
#define NG   (NPIX / 4)

#define P1_BLKX 148
#define P1_THR  128
#define P2_BLKX 256
#define P2_THR  256
#define P2_TOTAL (P2_BLKX * BN)

typedef unsigned long long ULL;

struct Scratch {
    float sums[BN][CC][NF];
    float counts[BN][CC];
    float dist[BN];
    unsigned int ticket;
};
__device__ Scratch g_s;

__device__ __forceinline__ ULL fadd2(ULL a, ULL b) {
    ULL d;
    asm("add.rn.f32x2 %0, %1, %2;" : "=l"(d) : "l"(a), "l"(b));
    return d;
}
__device__ __forceinline__ ULL pack2(float lo, float hi) {
    ULL r;
    asm("mov.b64 %0, {%1, %2};" : "=l"(r) : "f"(lo), "f"(hi));
    return r;
}
__device__ __forceinline__ void unpack2(ULL v, float& lo, float& hi) {
    asm("mov.b64 {%0, %1}, %2;" : "=f"(lo), "=f"(hi) : "l"(v));
}
// if (lab == c): acc0..3 += pr0..3 (f32x2 each), cnt += inc. 1 setp + 5 pred adds.
__device__ __forceinline__ void acc_if_eq(ULL& a0, ULL& a1, ULL& a2, ULL& a3,
                                          int& cnt, int lab, int c, int inc,
                                          ULL p0, ULL p1, ULL p2, ULL p3) {
    asm("{ .reg .pred p; setp.eq.s32 p, %5, %6;\n\t"
        "@p add.rn.f32x2 %0, %0, %8;\n\t"
        "@p add.rn.f32x2 %1, %1, %9;\n\t"
        "@p add.rn.f32x2 %2, %2, %10;\n\t"
        "@p add.rn.f32x2 %3, %3, %11;\n\t"
        "@p add.s32 %4, %4, %7; }"
        : "+l"(a0), "+l"(a1), "+l"(a2), "+l"(a3), "+r"(cnt)
        : "r"(lab), "r"(c), "r"(inc), "l"(p0), "l"(p1), "l"(p2), "l"(p3));
}
__device__ __forceinline__ float f4get(const float4 v, int i) {
    return i == 0 ? v.x : i == 1 ? v.y : i == 2 ? v.z : v.w;
}
__device__ __forceinline__ int i4get(const int4 v, int i) {
    return i == 0 ? v.x : i == 1 ? v.y : i == 2 ? v.z : v.w;
}
// sqrt on the FMA pipe only: bit-hack rsqrt seed + 3 Newton steps.
// |rel err| ~1e-10 after 3 iters; returns exactly 0 for x == 0.
__device__ __forceinline__ float fsqrt_fma(float x) {
    float y = __int_as_float(0x5f3759df - (__float_as_int(x) >> 1));
    float h = 0.5f * x;
    y = y * fmaf(-h, y * y, 1.5f);
    y = y * fmaf(-h, y * y, 1.5f);
    y = y * fmaf(-h, y * y, 1.5f);
    return x * y;
}

// ---------------------------------------------------------------------------
// Pass 1: per-cluster counts + feature sums (predicated-add one-hot).
// ---------------------------------------------------------------------------
__global__ void __launch_bounds__(P1_THR) k_pass1(const float* __restrict__ pred,
                                                  const int* __restrict__ tgt) {
    const int b = blockIdx.y;
    const float4* p = (const float4*)(pred + (size_t)b * NF * NPIX);
    const int4*   g = (const int4*)(tgt + (size_t)b * NPIX);

    ULL acc[CC][4];
    int cnta = 0, cntb = 0;  // byte-packed counts, clusters 0-3 / 4-7
#pragma unroll
    for (int c = 0; c < CC; c++)
#pragma unroll
        for (int k = 0; k < 4; k++) acc[c][k] = 0ull;

    for (int n = blockIdx.x * P1_THR + threadIdx.x; n < NG;
         n += P1_BLKX * P1_THR) {
        int4 lab4 = g[n];
        float4 v[NF];
#pragma unroll
        for (int f = 0; f < NF; f++) v[f] = p[f * NG + n];
#pragma unroll
        for (int px = 0; px < 4; px++) {
            int lab = i4get(lab4, px);
            ULL pr0 = pack2(f4get(v[0], px), f4get(v[1], px));
            ULL pr1 = pack2(f4get(v[2], px), f4get(v[3], px));
            ULL pr2 = pack2(f4get(v[4], px), f4get(v[5], px));
            ULL pr3 = pack2(f4get(v[6], px), f4get(v[7], px));
#pragma unroll
            for (int c = 0; c < 4; c++)
                acc_if_eq(acc[c][0], acc[c][1], acc[c][2], acc[c][3],
                          cnta, lab, c, 1 << (8 * c), pr0, pr1, pr2, pr3);
#pragma unroll
            for (int c = 4; c < 8; c++)
                acc_if_eq(acc[c][0], acc[c][1], acc[c][2], acc[c][3],
                          cntb, lab, c, 1 << (8 * (c - 4)), pr0, pr1, pr2, pr3);
        }
    }

    // unpack counts, warp tree-reduce everything
    int icnt[CC];
#pragma unroll
    for (int c = 0; c < 4; c++) {
        icnt[c]     = (cnta >> (8 * c)) & 0xFF;
        icnt[c + 4] = (cntb >> (8 * c)) & 0xFF;
    }
#pragma unroll
    for (int c = 0; c < CC; c++) {
#pragma unroll
        for (int k = 0; k < 4; k++) {
            ULL x = acc[c][k];
#pragma unroll
            for (int o = 16; o > 0; o >>= 1)
                x = fadd2(x, __shfl_down_sync(0xffffffffu, x, o));
            acc[c][k] = x;
        }
        int ic = icnt[c];
#pragma unroll
        for (int o = 16; o > 0; o >>= 1) ic += __shfl_down_sync(0xffffffffu, ic, o);
        icnt[c] = ic;
    }

    __shared__ float sw[4][72];
    int tid = threadIdx.x, wid = tid >> 5, lane = tid & 31;
    if (lane == 0) {
#pragma unroll
        for (int c = 0; c < CC; c++) {
#pragma unroll
            for (int k = 0; k < 4; k++) {
                float lo, hi;
                unpack2(acc[c][k], lo, hi);
                sw[wid][c * NF + 2 * k]     = lo;
                sw[wid][c * NF + 2 * k + 1] = hi;
            }
            sw[wid][64 + c] = (float)icnt[c];
        }
    }
    __syncthreads();
    if (tid < 72) {
        float s = sw[0][tid] + sw[1][tid] + sw[2][tid] + sw[3][tid];
        if (tid < 64)
            atomicAdd(&((float*)g_s.sums)[b * 64 + tid], s);
        else
            atomicAdd(&g_s.counts[b][tid - 64], s);
    }
}

// ---------------------------------------------------------------------------
// Pass 2: hinge distance to own-cluster mean. One pixel-group per thread,
// FMA-pipe sqrt. Finalize fused via last-block ticket.
// ---------------------------------------------------------------------------
__global__ void __launch_bounds__(P2_THR) k_pass2(const float* __restrict__ pred,
                                                  const int* __restrict__ tgt,
                                                  float* __restrict__ out) {
    const int b = blockIdx.y;
    __shared__ float4 smean0[CC];  // features 0-3 per label
    __shared__ float4 smean1[CC];  // features 4-7 per label
    int tid = threadIdx.x;
    if (tid < 64) {
        int c = tid >> 3, f = tid & 7;
        float m = g_s.sums[b][c][f] / g_s.counts[b][c];
        float* base = (f < 4) ? (float*)&smean0[c] : (float*)&smean1[c];
        base[f & 3] = m;
    }
    __syncthreads();

    const float4* p = (const float4*)(pred + (size_t)b * NF * NPIX);
    const int4*   g = (const int4*)(tgt + (size_t)b * NPIX);

    // exactly one group per thread: P2_BLKX * P2_THR == NG
    const int n = blockIdx.x * P2_THR + tid;
    int4 lab4 = g[n];
    float4 v[NF];
#pragma unroll
    for (int f = 0; f < NF; f++) v[f] = p[f * NG + n];

    float local = 0.f;
#pragma unroll
    for (int px = 0; px < 4; px++) {
        int lab = i4get(lab4, px);
        float4 m0 = smean0[lab];
        float4 m1 = smean1[lab];
        float d2 = 0.f, d;
        d = m0.x - f4get(v[0], px); d2 = fmaf(d, d, d2);
        d = m0.y - f4get(v[1], px); d2 = fmaf(d, d, d2);
        d = m0.z - f4get(v[2], px); d2 = fmaf(d, d, d2);
        d = m0.w - f4get(v[3], px); d2 = fmaf(d, d, d2);
        d = m1.x - f4get(v[4], px); d2 = fmaf(d, d, d2);
        d = m1.y - f4get(v[5], px); d2 = fmaf(d, d, d2);
        d = m1.z - f4get(v[6], px); d2 = fmaf(d, d, d2);
        d = m1.w - f4get(v[7], px); d2 = fmaf(d, d, d2);
        float t = fsqrt_fma(d2) - 0.5f;          // DELTA_V
        t = fminf(fmaxf(t, 0.f), 100000.f);
        local = fmaf(t, t, local);
    }

#pragma unroll
    for (int o = 16; o > 0; o >>= 1)
        local += __shfl_down_sync(0xffffffffu, local, o);
    __shared__ float sred[8];
    int wid = tid >> 5, lane = tid & 31;
    if (lane == 0) sred[wid] = local;
    __syncthreads();
    if (tid == 0) {
        float s = 0.f;
#pragma unroll
        for (int w = 0; w < 8; w++) s += sred[w];
        atomicAdd(&g_s.dist[b], s);
    }

    // ---- last-block finalize ----
    __shared__ bool s_last;
    __threadfence();
    if (tid == 0) {
        unsigned int t = atomicAdd(&g_s.ticket, 1u);
        s_last = (t == P2_TOTAL - 1);
    }
    __syncthreads();
    if (!s_last) return;

    __shared__ float smu[BN][CC][NF];
    __shared__ float s_ldist[BN], s_lreg[BN], s_inv[BN];
    {
        int bb = tid >> 6, i = (tid >> 3) & 7, j = tid & 7;
        smu[bb][i][j] = __ldcg(&g_s.sums[bb][i][j]) / __ldcg(&g_s.counts[bb][i]);
    }
    if (tid < BN) { s_ldist[tid] = 0.f; s_lreg[tid] = 0.f; s_inv[tid] = 0.f; }
    __syncthreads();

    {
        int bb = tid >> 6, i = (tid >> 3) & 7, j = tid & 7;
        if (i != j) {
            float d2 = 0.f;
#pragma unroll
            for (int f = 0; f < NF; f++) {
                float d = smu[bb][i][f] - smu[bb][j][f];
                d2 = fmaf(d, d, d2);
            }
            float t = 3.0f - sqrtf(d2);          // 2 * DELTA_D
            t = fminf(fmaxf(t, 0.f), 100000.f);
            atomicAdd(&s_ldist[bb], t * t);
        } else {
            float d2 = 0.f;
#pragma unroll
            for (int f = 0; f < NF; f++)
                d2 = fmaf(smu[bb][i][f], smu[bb][i][f], d2);
            atomicAdd(&s_lreg[bb], sqrtf(d2));
            atomicAdd(&s_inv[bb], 1.0f / __ldcg(&g_s.counts[bb][i]));
        }
    }
    __syncthreads();

    if (tid == 0) {
        float total = 0.f;
#pragma unroll
        for (int q = 0; q < BN; q++) {
            float dq = __ldcg(&g_s.dist[q]);
            float l_var  = dq * s_inv[q] / (float)CC;
            float l_dist = s_ldist[q] / (float)(CC * (CC - 1));
            float l_reg  = s_lreg[q] / (float)CC;
            total += l_var + l_dist + 0.001f * l_reg;
        }
        out[0] = total / (float)BN;
    }
}

extern "C" void kernel_launch(void* const* d_in, const int* in_sizes, int n_in,
                              void* d_out, int out_size) {
    const float* pred = (const float*)d_in[0];
    const int*   tgt  = (const int*)d_in[1];
    float*       out  = (float*)d_out;
    (void)in_sizes; (void)n_in; (void)out_size;

    void* scratch_ptr = nullptr;
    cudaGetSymbolAddress(&scratch_ptr, g_s);
    cudaMemsetAsync(scratch_ptr, 0, sizeof(Scratch));

    dim3 grid1(P1_BLKX, BN);
    k_pass1<<<grid1, P1_THR>>>(pred, tgt);
    dim3 grid2(P2_BLKX, BN);
    k_pass2<<<grid2, P2_THR>>>(pred, tgt, out);
}

// round 8
// speedup vs baseline: 1.1131x; 1.0649x over previous
#include <cuda_runtime.h>

#define BN   4
#define NF   8
#define CC   8
#define NPIX (512 * 512)
#define NG   (NPIX / 4)        // 65536 groups (of 4 pixels) per image

#define GPB  1024              // groups per block
#define BX   (NG / GPB)        // 64 blocks per image
#define GT   256               // groups per tile
#define NT   (GPB / GT)        // 4 tiles per block
#define THR  256

#define TILE_PRED   (GT * 16)                       // 4096 B per feature slice
#define STAGE_BYTES (TILE_PRED * NF + GT * 16)      // 36864 B
#define SMEM_DYN    (2 * STAGE_BYTES + 64)
#define TX_BYTES    STAGE_BYTES
#define P2_TOTAL    (BX * BN)

typedef unsigned long long ULL;

struct Scratch {
    float sums[BN][CC][NF];
    float counts[BN][CC];
    float dist[BN];
    unsigned int ticket;
};
__device__ Scratch g_s;

// ---------------- PTX helpers ----------------
__device__ __forceinline__ unsigned sm32(const void* p) {
    unsigned r;
    asm("{ .reg .u64 t; cvta.to.shared.u64 t, %1; cvt.u32.u64 %0, t; }"
        : "=r"(r) : "l"(p));
    return r;
}
__device__ __forceinline__ void mbar_init(unsigned a, int cnt) {
    asm volatile("mbarrier.init.shared.b64 [%0], %1;" :: "r"(a), "r"(cnt) : "memory");
}
__device__ __forceinline__ void mbar_expect(unsigned a, unsigned bytes) {
    asm volatile("mbarrier.arrive.expect_tx.shared.b64 _, [%0], %1;"
                 :: "r"(a), "r"(bytes) : "memory");
}
__device__ __forceinline__ void mbar_wait(unsigned a, unsigned ph) {
    unsigned done;
    asm volatile(
        "{ .reg .pred p;\n\t"
        "mbarrier.try_wait.parity.acquire.cta.shared::cta.b64 p, [%1], %2;\n\t"
        "selp.b32 %0, 1, 0, p; }"
        : "=r"(done) : "r"(a), "r"(ph) : "memory");
    while (!done) {
        asm volatile(
            "{ .reg .pred p;\n\t"
            "mbarrier.try_wait.parity.acquire.cta.shared::cta.b64 p, [%1], %2, 0x989680;\n\t"
            "selp.b32 %0, 1, 0, p; }"
            : "=r"(done) : "r"(a), "r"(ph) : "memory");
    }
}
__device__ __forceinline__ void bulk_g2s(unsigned dst, const void* src,
                                         unsigned bytes, unsigned mbar) {
    asm volatile(
        "cp.async.bulk.shared::cluster.global.mbarrier::complete_tx::bytes "
        "[%0], [%1], %2, [%3];"
        :: "r"(dst), "l"(src), "r"(bytes), "r"(mbar) : "memory");
}
__device__ __forceinline__ void issue_tile(unsigned dst, const char* predb,
                                           const char* tgtb, int gstart,
                                           unsigned mbar) {
#pragma unroll
    for (int f = 0; f < NF; f++)
        bulk_g2s(dst + f * TILE_PRED,
                 predb + (size_t)f * NPIX * 4 + (size_t)gstart * 16,
                 TILE_PRED, mbar);
    bulk_g2s(dst + NF * TILE_PRED, tgtb + (size_t)gstart * 16, GT * 16, mbar);
}
__device__ __forceinline__ ULL fadd2(ULL a, ULL b) {
    ULL d;
    asm("add.rn.f32x2 %0, %1, %2;" : "=l"(d) : "l"(a), "l"(b));
    return d;
}
__device__ __forceinline__ ULL pack2(float lo, float hi) {
    ULL r;
    asm("mov.b64 %0, {%1, %2};" : "=l"(r) : "f"(lo), "f"(hi));
    return r;
}
__device__ __forceinline__ void unpack2(ULL v, float& lo, float& hi) {
    asm("mov.b64 {%0, %1}, %2;" : "=f"(lo), "=f"(hi) : "l"(v));
}
__device__ __forceinline__ void acc_if_eq(ULL& a0, ULL& a1, ULL& a2, ULL& a3,
                                          int& cnt, int lab, int c, int inc,
                                          ULL p0, ULL p1, ULL p2, ULL p3) {
    asm("{ .reg .pred p; setp.eq.s32 p, %5, %6;\n\t"
        "@p add.rn.f32x2 %0, %0, %8;\n\t"
        "@p add.rn.f32x2 %1, %1, %9;\n\t"
        "@p add.rn.f32x2 %2, %2, %10;\n\t"
        "@p add.rn.f32x2 %3, %3, %11;\n\t"
        "@p add.s32 %4, %4, %7; }"
        : "+l"(a0), "+l"(a1), "+l"(a2), "+l"(a3), "+r"(cnt)
        : "r"(lab), "r"(c), "r"(inc), "l"(p0), "l"(p1), "l"(p2), "l"(p3));
}
__device__ __forceinline__ float f4get(const float4 v, int i) {
    return i == 0 ? v.x : i == 1 ? v.y : i == 2 ? v.z : v.w;
}
__device__ __forceinline__ int i4get(const int4 v, int i) {
    return i == 0 ? v.x : i == 1 ? v.y : i == 2 ? v.z : v.w;
}

// ---------------------------------------------------------------------------
// Pass 1: TMA-tiled per-cluster counts + feature sums.
// ---------------------------------------------------------------------------
__global__ void __launch_bounds__(THR) k_pass1(const float* __restrict__ pred,
                                               const int* __restrict__ tgt) {
    extern __shared__ char sm[];
    const int tid = threadIdx.x;
    const int b = blockIdx.y;
    const int g0 = blockIdx.x * GPB;
    const char* predb = (const char*)pred + (size_t)b * NF * NPIX * 4;
    const char* tgtb  = (const char*)tgt + (size_t)b * NPIX * 4;

    unsigned sbase = sm32(sm);
    unsigned mbar  = sbase + 2 * STAGE_BYTES;
    if (tid == 0) { mbar_init(mbar, 1); mbar_init(mbar + 8, 1); }
    __syncthreads();
    if (tid == 0) {
#pragma unroll
        for (int s = 0; s < 2; s++) {
            mbar_expect(mbar + 8 * s, TX_BYTES);
            issue_tile(sbase + s * STAGE_BYTES, predb, tgtb, g0 + s * GT,
                       mbar + 8 * s);
        }
    }

    ULL acc[CC][4];
    int cnta = 0, cntb = 0;
#pragma unroll
    for (int c = 0; c < CC; c++)
#pragma unroll
        for (int k = 0; k < 4; k++) acc[c][k] = 0ull;

#pragma unroll
    for (int t = 0; t < NT; t++) {
        int st = t & 1;
        mbar_wait(mbar + 8 * st, (t >> 1) & 1);

        const char* stg = sm + st * STAGE_BYTES;
        int4 lab4 = ((const int4*)(stg + NF * TILE_PRED))[tid];
        float4 v[NF];
#pragma unroll
        for (int f = 0; f < NF; f++)
            v[f] = ((const float4*)(stg + f * TILE_PRED))[tid];

#pragma unroll
        for (int px = 0; px < 4; px++) {
            int lab = i4get(lab4, px);
            ULL pr0 = pack2(f4get(v[0], px), f4get(v[1], px));
            ULL pr1 = pack2(f4get(v[2], px), f4get(v[3], px));
            ULL pr2 = pack2(f4get(v[4], px), f4get(v[5], px));
            ULL pr3 = pack2(f4get(v[6], px), f4get(v[7], px));
#pragma unroll
            for (int c = 0; c < 4; c++)
                acc_if_eq(acc[c][0], acc[c][1], acc[c][2], acc[c][3],
                          cnta, lab, c, 1 << (8 * c), pr0, pr1, pr2, pr3);
#pragma unroll
            for (int c = 4; c < 8; c++)
                acc_if_eq(acc[c][0], acc[c][1], acc[c][2], acc[c][3],
                          cntb, lab, c, 1 << (8 * (c - 4)), pr0, pr1, pr2, pr3);
        }
        __syncthreads();   // everyone done with buffer st
        if (tid == 0 && t + 2 < NT) {
            mbar_expect(mbar + 8 * st, TX_BYTES);
            issue_tile(sbase + st * STAGE_BYTES, predb, tgtb, g0 + (t + 2) * GT,
                       mbar + 8 * st);
        }
    }

    // reduce
    int icnt[CC];
#pragma unroll
    for (int c = 0; c < 4; c++) {
        icnt[c]     = (cnta >> (8 * c)) & 0xFF;
        icnt[c + 4] = (cntb >> (8 * c)) & 0xFF;
    }
#pragma unroll
    for (int c = 0; c < CC; c++) {
#pragma unroll
        for (int k = 0; k < 4; k++) {
            ULL x = acc[c][k];
#pragma unroll
            for (int o = 16; o > 0; o >>= 1)
                x = fadd2(x, __shfl_down_sync(0xffffffffu, x, o));
            acc[c][k] = x;
        }
        int ic = icnt[c];
#pragma unroll
        for (int o = 16; o > 0; o >>= 1) ic += __shfl_down_sync(0xffffffffu, ic, o);
        icnt[c] = ic;
    }

    __shared__ float sw[8][72];
    int wid = tid >> 5, lane = tid & 31;
    if (lane == 0) {
#pragma unroll
        for (int c = 0; c < CC; c++) {
#pragma unroll
            for (int k = 0; k < 4; k++) {
                float lo, hi;
                unpack2(acc[c][k], lo, hi);
                sw[wid][c * NF + 2 * k]     = lo;
                sw[wid][c * NF + 2 * k + 1] = hi;
            }
            sw[wid][64 + c] = (float)icnt[c];
        }
    }
    __syncthreads();
    if (tid < 72) {
        float s = 0.f;
#pragma unroll
        for (int w = 0; w < 8; w++) s += sw[w][tid];
        if (tid < 64)
            atomicAdd(&((float*)g_s.sums)[b * 64 + tid], s);
        else
            atomicAdd(&g_s.counts[b][tid - 64], s);
    }
}

// ---------------------------------------------------------------------------
// Pass 2: TMA-tiled hinge distance to own-cluster mean + fused finalize.
// ---------------------------------------------------------------------------
__global__ void __launch_bounds__(THR) k_pass2(const float* __restrict__ pred,
                                               const int* __restrict__ tgt,
                                               float* __restrict__ out) {
    extern __shared__ char sm[];
    const int tid = threadIdx.x;
    const int b = blockIdx.y;
    const int g0 = blockIdx.x * GPB;
    const char* predb = (const char*)pred + (size_t)b * NF * NPIX * 4;
    const char* tgtb  = (const char*)tgt + (size_t)b * NPIX * 4;

    unsigned sbase = sm32(sm);
    unsigned mbar  = sbase + 2 * STAGE_BYTES;

    __shared__ float4 smean0[CC];   // features 0-3 per label
    __shared__ float4 smean1[CC];   // features 4-7 per label
    if (tid == 0) { mbar_init(mbar, 1); mbar_init(mbar + 8, 1); }
    if (tid < 64) {
        int c = tid >> 3, f = tid & 7;
        float m = g_s.sums[b][c][f] / g_s.counts[b][c];
        float* base = (f < 4) ? (float*)&smean0[c] : (float*)&smean1[c];
        base[f & 3] = m;
    }
    __syncthreads();
    if (tid == 0) {
#pragma unroll
        for (int s = 0; s < 2; s++) {
            mbar_expect(mbar + 8 * s, TX_BYTES);
            issue_tile(sbase + s * STAGE_BYTES, predb, tgtb, g0 + s * GT,
                       mbar + 8 * s);
        }
    }

    float local = 0.f;
#pragma unroll
    for (int t = 0; t < NT; t++) {
        int st = t & 1;
        mbar_wait(mbar + 8 * st, (t >> 1) & 1);

        const char* stg = sm + st * STAGE_BYTES;
        int4 lab4 = ((const int4*)(stg + NF * TILE_PRED))[tid];
        float4 v[NF];
#pragma unroll
        for (int f = 0; f < NF; f++)
            v[f] = ((const float4*)(stg + f * TILE_PRED))[tid];

#pragma unroll
        for (int px = 0; px < 4; px++) {
            int lab = i4get(lab4, px);
            float4 m0 = smean0[lab];
            float4 m1 = smean1[lab];
            float d2 = 0.f, d;
            d = m0.x - f4get(v[0], px); d2 = fmaf(d, d, d2);
            d = m0.y - f4get(v[1], px); d2 = fmaf(d, d, d2);
            d = m0.z - f4get(v[2], px); d2 = fmaf(d, d, d2);
            d = m0.w - f4get(v[3], px); d2 = fmaf(d, d, d2);
            d = m1.x - f4get(v[4], px); d2 = fmaf(d, d, d2);
            d = m1.y - f4get(v[5], px); d2 = fmaf(d, d, d2);
            d = m1.z - f4get(v[6], px); d2 = fmaf(d, d, d2);
            d = m1.w - f4get(v[7], px); d2 = fmaf(d, d, d2);
            float tt = sqrtf(d2) - 0.5f;           // DELTA_V
            tt = fminf(fmaxf(tt, 0.f), 100000.f);
            local = fmaf(tt, tt, local);
        }
        __syncthreads();
        if (tid == 0 && t + 2 < NT) {
            mbar_expect(mbar + 8 * st, TX_BYTES);
            issue_tile(sbase + st * STAGE_BYTES, predb, tgtb, g0 + (t + 2) * GT,
                       mbar + 8 * st);
        }
    }

#pragma unroll
    for (int o = 16; o > 0; o >>= 1)
        local += __shfl_down_sync(0xffffffffu, local, o);
    __shared__ float sred[8];
    int wid = tid >> 5, lane = tid & 31;
    if (lane == 0) sred[wid] = local;
    __syncthreads();
    if (tid == 0) {
        float s = 0.f;
#pragma unroll
        for (int w = 0; w < 8; w++) s += sred[w];
        atomicAdd(&g_s.dist[b], s);
    }

    // ---- last-block finalize ----
    __shared__ bool s_last;
    __threadfence();
    if (tid == 0) {
        unsigned int t = atomicAdd(&g_s.ticket, 1u);
        s_last = (t == P2_TOTAL - 1);
    }
    __syncthreads();
    if (!s_last) return;

    __shared__ float smu[BN][CC][NF];
    __shared__ float s_ldist[BN], s_lreg[BN], s_inv[BN];
    {
        int bb = tid >> 6, i = (tid >> 3) & 7, j = tid & 7;
        smu[bb][i][j] = __ldcg(&g_s.sums[bb][i][j]) / __ldcg(&g_s.counts[bb][i]);
    }
    if (tid < BN) { s_ldist[tid] = 0.f; s_lreg[tid] = 0.f; s_inv[tid] = 0.f; }
    __syncthreads();

    {
        int bb = tid >> 6, i = (tid >> 3) & 7, j = tid & 7;
        if (i != j) {
            float d2 = 0.f;
#pragma unroll
            for (int f = 0; f < NF; f++) {
                float d = smu[bb][i][f] - smu[bb][j][f];
                d2 = fmaf(d, d, d2);
            }
            float t = 3.0f - sqrtf(d2);            // 2 * DELTA_D
            t = fminf(fmaxf(t, 0.f), 100000.f);
            atomicAdd(&s_ldist[bb], t * t);
        } else {
            float d2 = 0.f;
#pragma unroll
            for (int f = 0; f < NF; f++)
                d2 = fmaf(smu[bb][i][f], smu[bb][i][f], d2);
            atomicAdd(&s_lreg[bb], sqrtf(d2));
            atomicAdd(&s_inv[bb], 1.0f / __ldcg(&g_s.counts[bb][i]));
        }
    }
    __syncthreads();

    if (tid == 0) {
        float total = 0.f;
#pragma unroll
        for (int q = 0; q < BN; q++) {
            float dq = __ldcg(&g_s.dist[q]);
            float l_var  = dq * s_inv[q] / (float)CC;
            float l_dist = s_ldist[q] / (float)(CC * (CC - 1));
            float l_reg  = s_lreg[q] / (float)CC;
            total += l_var + l_dist + 0.001f * l_reg;
        }
        out[0] = total / (float)BN;
    }
}

extern "C" void kernel_launch(void* const* d_in, const int* in_sizes, int n_in,
                              void* d_out, int out_size) {
    const float* pred = (const float*)d_in[0];
    const int*   tgt  = (const int*)d_in[1];
    float*       out  = (float*)d_out;
    (void)in_sizes; (void)n_in; (void)out_size;

    static bool attr_done = false;
    if (!attr_done) {
        cudaFuncSetAttribute(k_pass1, cudaFuncAttributeMaxDynamicSharedMemorySize,
                             SMEM_DYN);
        cudaFuncSetAttribute(k_pass2, cudaFuncAttributeMaxDynamicSharedMemorySize,
                             SMEM_DYN);
        attr_done = true;
    }

    void* scratch_ptr = nullptr;
    cudaGetSymbolAddress(&scratch_ptr, g_s);
    cudaMemsetAsync(scratch_ptr, 0, sizeof(Scratch));

    dim3 grid(BX, BN);
    k_pass1<<<grid, THR, SMEM_DYN>>>(pred, tgt);
    k_pass2<<<grid, THR, SMEM_DYN>>>(pred, tgt, out);
}